// round 5
// baseline (speedup 1.0000x reference)
#include <cuda_runtime.h>

// GINConv fused: out = A @ (X @ W)  (reassociated from (A@X) @ W)
// N=100000 nodes, E edges (CSR), D_IN = D_OUT = 32.

#define MAX_N 100000
#define D 32

// Scratch for Y = X @ W  (12.8 MB, fits in L2) — static to obey no-alloc rule.
__device__ __align__(16) float g_Y[MAX_N * D];

// packed f32x2 accumulate: a += b (two fp32 adds in one instruction)
__device__ __forceinline__ void add2(unsigned long long& a, unsigned long long b) {
    asm("add.rn.f32x2 %0, %0, %1;" : "+l"(a) : "l"(b));
}

// ---------------------------------------------------------------------------
// Kernel 1: Y = X @ W.  One warp per 4 rows; lane (g,s) computes float4 of
// outputs for row base+g, cols s*4..s*4+3.
// ---------------------------------------------------------------------------
__global__ void __launch_bounds__(256) gin_transform(
    const float* __restrict__ X, const float* __restrict__ W, int n)
{
    __shared__ __align__(16) float Ws[D * D];        // 4 KB
    __shared__ __align__(16) float Xs[8][4 * 36];    // 4 rows/warp, pad stride 36

    int tid = threadIdx.x;
    for (int i = tid; i < D * D; i += blockDim.x) Ws[i] = W[i];
    __syncthreads();

    int lane = tid & 31;
    int wip  = tid >> 5;
    int warp = blockIdx.x * 8 + wip;
    int row4 = warp * 4;
    if (row4 >= n) return;

    int g = lane >> 3, s = lane & 7;
    int r = row4 + g;

    float4 xv = make_float4(0.f, 0.f, 0.f, 0.f);
    if (r < n) xv = ((const float4*)X)[r * 8 + s];       // coalesced 512B/warp
    float* xrow = &Xs[wip][g * 36];
    *((float4*)(xrow + s * 4)) = xv;
    __syncwarp();

    float4 acc = make_float4(0.f, 0.f, 0.f, 0.f);
    #pragma unroll
    for (int k = 0; k < D; k++) {
        float  xk = xrow[k];
        float4 wr = ((const float4*)Ws)[k * 8 + s];      // LDS.128 broadcast
        acc.x = fmaf(xk, wr.x, acc.x);
        acc.y = fmaf(xk, wr.y, acc.y);
        acc.z = fmaf(xk, wr.z, acc.z);
        acc.w = fmaf(xk, wr.w, acc.w);
    }
    if (r < n) ((float4*)g_Y)[r * 8 + s] = acc;          // coalesced 512B/warp
}

// ---------------------------------------------------------------------------
// Kernel 2: out[r] = sum_{e in [rp[r], rp[r+1])} Y[ci[e]]
// One warp = 4 INDEPENDENT rows (one per 8-lane group). Each group chews its
// row 8 edges at a time; each gather LDG.128 covers one edge per group
// (4 edges / warp-instruction). 4 parallel latency chains per warp, no
// cross-group reduce, double-buffered index loads.
// ---------------------------------------------------------------------------
__global__ void __launch_bounds__(256) gin_aggregate(
    const int* __restrict__ rp, const int* __restrict__ ci,
    float* __restrict__ out, int n)
{
    int tid  = threadIdx.x;
    int lane = tid & 31;
    int grp  = lane >> 3, sub = lane & 7;
    int warp = blockIdx.x * 8 + (tid >> 5);

    int r = warp * 4 + grp;                 // this group's row
    bool valid = (r < n);

    int start = 0, end = 0;
    if (valid) { start = rp[r]; end = rp[r + 1]; }

    // warp-uniform trip count = max #8-edge batches over the 4 groups
    int nb = (end - start + 7) >> 3;
    nb = max(nb, __shfl_xor_sync(0xffffffffu, nb, 8));
    nb = max(nb, __shfl_xor_sync(0xffffffffu, nb, 16));

    const ulonglong2* __restrict__ Y2 = (const ulonglong2*)g_Y;  // row = 8 x 16B

    unsigned long long a01 = 0ull, a23 = 0ull;   // bitwise {0.f,0.f} pairs

    int e   = start;
    int myc = (e + sub < end) ? __ldg(&ci[e + sub]) : -1;

    for (int it = 0; it < nb; it++) {
        // prefetch next index chunk for this group's row
        int e2  = e + 8;
        int nxt = (it + 1 < nb && e2 + sub < end) ? __ldg(&ci[e2 + sub]) : -1;

        #pragma unroll
        for (int k = 0; k < 8; k++) {
            int c = __shfl_sync(0xffffffffu, myc, grp * 8 + k);
            if (c >= 0) {
                ulonglong2 v = __ldg(&Y2[c * 8 + sub]);  // LDG.128: 4 edges/warp
                add2(a01, v.x);
                add2(a23, v.y);
            }
        }
        myc = nxt;
        e   = e2;
    }

    if (valid) {
        ulonglong2 res;
        res.x = a01; res.y = a23;
        ((ulonglong2*)out)[r * 8 + sub] = res;   // full-warp 512B store (4 rows)
    }
}

// ---------------------------------------------------------------------------
extern "C" void kernel_launch(void* const* d_in, const int* in_sizes, int n_in,
                              void* d_out, int out_size)
{
    const float* X  = (const float*)d_in[0];
    const float* W  = (const float*)d_in[1];
    const int*   rp = (const int*)d_in[2];
    const int*   ci = (const int*)d_in[3];
    float*       out = (float*)d_out;

    int n = in_sizes[0] / D;   // number of nodes

    const int THREADS = 256;
    int tblocks = (n + 31) / 32;   // 4 rows/warp, 8 warps/block
    int ablocks = (n + 31) / 32;   // 4 rows/warp, 8 warps/block

    gin_transform<<<tblocks, THREADS>>>(X, W, n);
    gin_aggregate<<<ablocks, THREADS>>>(rp, ci, out, n);
}

// round 7
// speedup vs baseline: 1.0907x; 1.0907x over previous
#include <cuda_runtime.h>

// GINConv fused: out = A @ (X @ W)  (reassociated from (A@X) @ W)
// N=100000 nodes, E edges (CSR), D_IN = D_OUT = 32.
// R6: EDGE-BALANCED aggregation — each warp owns 32 consecutive edges,
// segmented accumulation with red.global.add.v4.f32 flushes.

#define MAX_N 100000
#define D 32

// Scratch for Y = X @ W  (12.8 MB, fits in L2) — static to obey no-alloc rule.
__device__ __align__(16) float g_Y[MAX_N * D];

// packed f32x2 accumulate: a += b (two fp32 adds in one instruction)
__device__ __forceinline__ void add2(unsigned long long& a, unsigned long long b) {
    asm("add.rn.f32x2 %0, %0, %1;" : "+l"(a) : "l"(b));
}

// ---------------------------------------------------------------------------
// Kernel 1: Y = X @ W, and zero-init `out` (atomic accumulation target).
// One warp per 4 rows; lane (g,s) computes float4 for row base+g, cols 4s..4s+3.
// ---------------------------------------------------------------------------
__global__ void __launch_bounds__(256) gin_transform(
    const float* __restrict__ X, const float* __restrict__ W,
    float* __restrict__ out, int n)
{
    __shared__ __align__(16) float Ws[D * D];        // 4 KB
    __shared__ __align__(16) float Xs[8][4 * 36];    // 4 rows/warp, pad stride 36

    int tid = threadIdx.x;
    for (int i = tid; i < D * D; i += blockDim.x) Ws[i] = W[i];
    __syncthreads();

    int lane = tid & 31;
    int wip  = tid >> 5;
    int warp = blockIdx.x * 8 + wip;
    int row4 = warp * 4;
    if (row4 >= n) return;

    int g = lane >> 3, s = lane & 7;
    int r = row4 + g;

    float4 xv = make_float4(0.f, 0.f, 0.f, 0.f);
    if (r < n) xv = ((const float4*)X)[r * 8 + s];       // coalesced 512B/warp
    float* xrow = &Xs[wip][g * 36];
    *((float4*)(xrow + s * 4)) = xv;
    __syncwarp();

    float4 acc = make_float4(0.f, 0.f, 0.f, 0.f);
    #pragma unroll
    for (int k = 0; k < D; k++) {
        float  xk = xrow[k];
        float4 wr = ((const float4*)Ws)[k * 8 + s];      // LDS.128 broadcast
        acc.x = fmaf(xk, wr.x, acc.x);
        acc.y = fmaf(xk, wr.y, acc.y);
        acc.z = fmaf(xk, wr.z, acc.z);
        acc.w = fmaf(xk, wr.w, acc.w);
    }
    if (r < n) {
        ((float4*)g_Y)[r * 8 + s] = acc;                 // coalesced 512B/warp
        ((float4*)out)[r * 8 + s] = make_float4(0.f, 0.f, 0.f, 0.f);
    }
}

// ---------------------------------------------------------------------------
// Kernel 2: edge-balanced aggregate. Warp w owns edges [32w, 32w+32).
// Lane l: binary-search row of edge 32w+l, load its column index.
// Group g (8 lanes) processes edges 32w+8g..+7: one LDG.128 gathers a full
// 128B Y row per edge (4 edges per warp-instruction across groups).
// Same-row runs accumulate in registers; flush per run with red.add.v4.f32.
// ---------------------------------------------------------------------------
__global__ void __launch_bounds__(256) gin_aggregate(
    const int* __restrict__ rp, const int* __restrict__ ci,
    float* __restrict__ out, int n, int nedges)
{
    int tid  = threadIdx.x;
    int lane = tid & 31;
    int grp  = lane >> 3, sub = lane & 7;
    int warp = blockIdx.x * 8 + (tid >> 5);

    int e = warp * 32 + lane;
    bool ev = (e < nedges);
    int ec = e < nedges ? e : nedges - 1;

    int myc = ev ? __ldg(&ci[ec]) : -1;       // coalesced index load

    // row(e) = largest r with rp[r] <= e  (rp[0]=0, rp[n]=E)
    int lo = 0, hi = n - 1;
    #pragma unroll 1
    while (lo < hi) {
        int mid = (lo + hi + 1) >> 1;
        if (__ldg(&rp[mid]) <= ec) lo = mid; else hi = mid - 1;
    }
    int myrow = lo;

    const ulonglong2* __restrict__ Y2 = (const ulonglong2*)g_Y;  // row = 8x16B

    unsigned long long a01 = 0ull, a23 = 0ull;
    int cur = -1;

    #pragma unroll
    for (int k = 0; k < 8; k++) {
        int src = grp * 8 + k;
        int c = __shfl_sync(0xffffffffu, myc,   src);
        int r = __shfl_sync(0xffffffffu, myrow, src);
        if (c < 0) continue;                 // tail edges (shfls done above)
        if (r != cur) {
            if (cur >= 0) {                  // flush previous run
                float* p = out + (size_t)cur * D + sub * 4;
                asm volatile("red.global.add.v4.f32 [%0], {%1, %2, %3, %4};"
                    :: "l"(p),
                       "f"(__uint_as_float((unsigned)a01)),
                       "f"(__uint_as_float((unsigned)(a01 >> 32))),
                       "f"(__uint_as_float((unsigned)a23)),
                       "f"(__uint_as_float((unsigned)(a23 >> 32)))
                    : "memory");
            }
            cur = r; a01 = 0ull; a23 = 0ull;
        }
        ulonglong2 v = __ldg(&Y2[(size_t)c * 8 + sub]);  // LDG.128: 4 edges/warp
        add2(a01, v.x);
        add2(a23, v.y);
    }
    if (cur >= 0) {
        float* p = out + (size_t)cur * D + sub * 4;
        asm volatile("red.global.add.v4.f32 [%0], {%1, %2, %3, %4};"
            :: "l"(p),
               "f"(__uint_as_float((unsigned)a01)),
               "f"(__uint_as_float((unsigned)(a01 >> 32))),
               "f"(__uint_as_float((unsigned)a23)),
               "f"(__uint_as_float((unsigned)(a23 >> 32)))
            : "memory");
    }
}

// ---------------------------------------------------------------------------
extern "C" void kernel_launch(void* const* d_in, const int* in_sizes, int n_in,
                              void* d_out, int out_size)
{
    const float* X  = (const float*)d_in[0];
    const float* W  = (const float*)d_in[1];
    const int*   rp = (const int*)d_in[2];
    const int*   ci = (const int*)d_in[3];
    float*       out = (float*)d_out;

    int n      = in_sizes[0] / D;   // number of nodes
    int nedges = in_sizes[3];       // E

    const int THREADS = 256;
    int tblocks = (n + 31) / 32;                       // 4 rows/warp, 8 warps
    int chunks  = (nedges + 31) / 32;                  // 32 edges per warp
    int ablocks = (chunks + 7) / 8;                    // 8 warps/block

    gin_transform<<<tblocks, THREADS>>>(X, W, out, n);
    gin_aggregate<<<ablocks, THREADS>>>(rp, ci, out, n, nedges);
}